// round 1
// baseline (speedup 1.0000x reference)
#include <cuda_runtime.h>

#define NHEADS 12
#define HD 64
#define BHT 96        // B * NHEADS
#define NSEQ 1024     // H*W
#define DIM 768
#define BROWS 8192    // B * NSEQ

// ---------------- scratch (device globals; no allocation) ----------------
__device__ float g_q[BHT * NSEQ * HD];
__device__ float g_k[BHT * NSEQ * HD];
__device__ float g_v[BHT * NSEQ * HD];
__device__ float g_relh[BHT * 32 * 32 * 32];
__device__ float g_relw[BHT * 32 * 32 * 32];
__device__ float g_o[BROWS * DIM];

// ---------------- SGEMM: BM=64, BN=128, BK=16, 256 threads, 4x8/thread ----
// MODE 1: A = Ain (x), epilogue scatters into g_q/g_k/g_v (qkv projection)
// MODE 0: A = g_o, epilogue writes C = A@B + bias (output projection)
template <int MODE>
__global__ void __launch_bounds__(256) sgemm_kernel(
    const float* __restrict__ Ain, const float* __restrict__ Bmat,
    const float* __restrict__ bias, float* __restrict__ C,
    int M, int N, int K)
{
    __shared__ float As[16][64];   // transposed: As[k][m]
    __shared__ float Bs[16][128];

    const float* A = (MODE == 0) ? (const float*)g_o : Ain;

    const int bm = blockIdx.y * 64;
    const int bn = blockIdx.x * 128;
    const int t  = threadIdx.x;
    const int ty = t >> 4;          // 0..15 -> rows ty*4..+3
    const int tx = t & 15;          // 0..15 -> cols tx*8..+7

    const int a_row = t >> 2;       // 0..63
    const int a_k   = (t & 3) * 4;  // 0,4,8,12
    const int b_k   = t >> 4;       // 0..15
    const int b_col = (t & 15) * 8; // 0..120

    float acc[4][8];
#pragma unroll
    for (int i = 0; i < 4; i++)
#pragma unroll
        for (int j = 0; j < 8; j++) acc[i][j] = 0.f;

    for (int k0 = 0; k0 < K; k0 += 16) {
        float4 av = *(const float4*)&A[(bm + a_row) * K + k0 + a_k];
        As[a_k + 0][a_row] = av.x;
        As[a_k + 1][a_row] = av.y;
        As[a_k + 2][a_row] = av.z;
        As[a_k + 3][a_row] = av.w;
        *(float4*)&Bs[b_k][b_col]     = *(const float4*)&Bmat[(k0 + b_k) * N + bn + b_col];
        *(float4*)&Bs[b_k][b_col + 4] = *(const float4*)&Bmat[(k0 + b_k) * N + bn + b_col + 4];
        __syncthreads();

#pragma unroll
        for (int kk = 0; kk < 16; kk++) {
            float4 a  = *(const float4*)&As[kk][ty * 4];
            float4 b0 = *(const float4*)&Bs[kk][tx * 8];
            float4 b1 = *(const float4*)&Bs[kk][tx * 8 + 4];
            float av4[4] = {a.x, a.y, a.z, a.w};
            float bv8[8] = {b0.x, b0.y, b0.z, b0.w, b1.x, b1.y, b1.z, b1.w};
#pragma unroll
            for (int i = 0; i < 4; i++)
#pragma unroll
                for (int j = 0; j < 8; j++)
                    acc[i][j] += av4[i] * bv8[j];
        }
        __syncthreads();
    }

#pragma unroll
    for (int i = 0; i < 4; i++) {
        const int row = bm + ty * 4 + i;
#pragma unroll
        for (int j = 0; j < 8; j++) {
            const int col = bn + tx * 8 + j;
            float v = acc[i][j] + bias[col];
            if (MODE == 0) {
                C[row * N + col] = v;
            } else {
                // row = b*1024 + n ; col = which*768 + head*64 + d
                const int b = row >> 10;
                const int n = row & 1023;
                const int which = col / 768;
                const int rem = col - which * 768;
                const int head = rem >> 6;
                const int d = rem & 63;
                float* dst = (which == 0) ? g_q : (which == 1) ? g_k : g_v;
                dst[((b * NHEADS + head) * NSEQ + n) * HD + d] = v;
            }
        }
    }
}

// ---------------- relative position bias: one block per (bh, qh) ----------
__global__ void __launch_bounds__(256) rel_kernel(
    const float* __restrict__ rph,   // (63, 64)
    const float* __restrict__ rpw)   // (63, 64)
{
    __shared__ float qrow[32 * 64];   // q rows for qw=0..31 (unscaled q)
    __shared__ float rh[32 * 65];     // rel_pos_h rows qh..qh+31 (padded)
    __shared__ float rw[63 * 65];     // full rel_pos_w table (padded)

    const int bh = blockIdx.x;
    const int qh = blockIdx.y;
    const int t  = threadIdx.x;

    for (int i = t; i < 32 * 64; i += 256) {
        int row = i >> 6, d = i & 63;
        qrow[i] = g_q[((bh * NSEQ) + qh * 32 + row) * HD + d];
        rh[row * 65 + d] = rph[(qh + row) * 64 + d];
    }
    for (int i = t; i < 63 * 64; i += 256) {
        int row = i >> 6, d = i & 63;
        rw[row * 65 + d] = rpw[i];
    }
    __syncthreads();

    for (int o = t; o < 2048; o += 256) {
        if (o < 1024) {
            int qw = o >> 5, kh = o & 31;
            const float* a  = &qrow[qw * 64];
            const float* b2 = &rh[(31 - kh) * 65];   // idx = qh-kh+31 -> local row 31-kh
            float s = 0.f;
#pragma unroll
            for (int d = 0; d < 64; d++) s += a[d] * b2[d];
            g_relh[(((bh * 32 + qh) * 32 + qw) * 32) + kh] = s;
        } else {
            int oo = o - 1024;
            int qw = oo >> 5, kw = oo & 31;
            const float* a  = &qrow[qw * 64];
            const float* b2 = &rw[(qw - kw + 31) * 65];
            float s = 0.f;
#pragma unroll
            for (int d = 0; d < 64; d++) s += a[d] * b2[d];
            g_relw[(((bh * 32 + qh) * 32 + qw) * 32) + kw] = s;
        }
    }
}

// ---------------- fused attention: scores + softmax + PV ------------------
// block = (q-tile of 16 rows, bh). 256 threads.
#define QT 16
#define KT 128                       // key-tile for score phase
#define KV_STRIDE 132                // K^T smem stride (16B-aligned, conflict-free)

// smem layout (floats)
#define SM_QS     0                  // 16*64   = 1024
#define SM_RELH   1024               // 16*32   = 512
#define SM_RELW   1536               // 16*32   = 512
#define SM_SCORES 2048               // 16*1024 = 16384
#define SM_KVS    18432              // max(64*132, 64*64) = 8448
#define ATTN_SMEM_FLOATS (18432 + 64 * KV_STRIDE)
#define ATTN_SMEM_BYTES  (ATTN_SMEM_FLOATS * 4)

__global__ void __launch_bounds__(256) attn_kernel()
{
    extern __shared__ float sm[];
    float* qs     = sm + SM_QS;
    float* relh_s = sm + SM_RELH;
    float* relw_s = sm + SM_RELW;
    float* scores = sm + SM_SCORES;
    float* kvs    = sm + SM_KVS;

    const int qt = blockIdx.x;     // 0..63
    const int bh = blockIdx.y;     // 0..95
    const int t  = threadIdx.x;
    const float scale = 0.125f;    // 64^-0.5

    // load Q tile (unscaled)
    for (int i = t; i < QT * 64; i += 256)
        qs[i] = g_q[(bh * NSEQ + qt * QT) * HD + i];
    // load rel bias rows for the 16 q rows
    for (int i = t; i < QT * 32; i += 256) {
        int r = i >> 5, c = i & 31;
        int qn = qt * QT + r;
        int qh = qn >> 5, qw = qn & 31;
        int base = ((bh * 32 + qh) * 32 + qw) * 32 + c;
        relh_s[i] = g_relh[base];
        relw_s[i] = g_relw[base];
    }

    // ---------- score phase: S = scale*Q@K^T + bias, tiles of 128 keys ----
    const int r0  = (t >> 5) * 2;    // 2 rows per thread
    const int kn0 = (t & 31) * 4;    // 4 keys per thread
    for (int kt = 0; kt < NSEQ / KT; kt++) {
        __syncthreads();
        // load K tile transposed: kvs[d][kn], kn in [0,128)
#pragma unroll
        for (int f = 0; f < 8; f++) {
            int fi = t + 256 * f;           // float4 index over 128x64
            int row = fi >> 4;              // key row 0..127
            int col = (fi & 15) * 4;        // d
            float4 kv = *(const float4*)&g_k[(bh * NSEQ + kt * KT + row) * HD + col];
            kvs[(col + 0) * KV_STRIDE + row] = kv.x;
            kvs[(col + 1) * KV_STRIDE + row] = kv.y;
            kvs[(col + 2) * KV_STRIDE + row] = kv.z;
            kvs[(col + 3) * KV_STRIDE + row] = kv.w;
        }
        __syncthreads();

        float acc[2][4] = {{0.f, 0.f, 0.f, 0.f}, {0.f, 0.f, 0.f, 0.f}};
#pragma unroll 16
        for (int d = 0; d < 64; d++) {
            float q0 = qs[r0 * 64 + d];
            float q1 = qs[(r0 + 1) * 64 + d];
            float4 kf = *(const float4*)&kvs[d * KV_STRIDE + kn0];
            acc[0][0] += q0 * kf.x; acc[0][1] += q0 * kf.y;
            acc[0][2] += q0 * kf.z; acc[0][3] += q0 * kf.w;
            acc[1][0] += q1 * kf.x; acc[1][1] += q1 * kf.y;
            acc[1][2] += q1 * kf.z; acc[1][3] += q1 * kf.w;
        }
#pragma unroll
        for (int i = 0; i < 2; i++) {
            int r = r0 + i;
            float4 sv;
            float* pv = (float*)&sv;
#pragma unroll
            for (int j = 0; j < 4; j++) {
                int kn = kt * KT + kn0 + j;
                int kh = kn >> 5, kw = kn & 31;
                pv[j] = acc[i][j] * scale + relh_s[r * 32 + kh] + relw_s[r * 32 + kw];
            }
            *(float4*)&scores[r * 1024 + kt * KT + kn0] = sv;
        }
    }
    __syncthreads();

    // ---------- softmax: half-warp per row --------------------------------
    {
        const int w = t >> 5;
        const int lane = t & 31;
        const int row = w * 2 + (lane >> 4);
        const int l16 = lane & 15;
        float m = -1e30f;
#pragma unroll 8
        for (int i = 0; i < 64; i++)
            m = fmaxf(m, scores[row * 1024 + l16 + i * 16]);
#pragma unroll
        for (int off = 8; off; off >>= 1)
            m = fmaxf(m, __shfl_xor_sync(0xffffffffu, m, off));
        float sum = 0.f;
#pragma unroll 8
        for (int i = 0; i < 64; i++) {
            float e = __expf(scores[row * 1024 + l16 + i * 16] - m);
            scores[row * 1024 + l16 + i * 16] = e;
            sum += e;
        }
#pragma unroll
        for (int off = 8; off; off >>= 1)
            sum += __shfl_xor_sync(0xffffffffu, sum, off);
        float inv = 1.0f / sum;
#pragma unroll 8
        for (int i = 0; i < 64; i++)
            scores[row * 1024 + l16 + i * 16] *= inv;
    }

    // ---------- PV phase: O = P @ V, tiles of 64 keys ----------------------
    const int r = t >> 4;      // row 0..15
    const int g = t & 15;      // d-group: dims g*4..g*4+3
    float4 o = {0.f, 0.f, 0.f, 0.f};
    for (int vt = 0; vt < NSEQ / 64; vt++) {
        __syncthreads();
#pragma unroll
        for (int f = 0; f < 4; f++) {
            int fi = t + 256 * f;           // float4 index over 64x64
            int row = fi >> 4;
            int col = (fi & 15) * 4;
            *(float4*)&kvs[row * 64 + col] =
                *(const float4*)&g_v[(bh * NSEQ + vt * 64 + row) * HD + col];
        }
        __syncthreads();
#pragma unroll 16
        for (int kn = 0; kn < 64; kn++) {
            float p = scores[r * 1024 + vt * 64 + kn];
            float4 v = *(const float4*)&kvs[kn * 64 + g * 4];
            o.x += p * v.x; o.y += p * v.y; o.z += p * v.z; o.w += p * v.w;
        }
    }

    // write to g_o with layout [b][n][head][d] = (8192, 768)
    const int b = bh / NHEADS;
    const int head = bh % NHEADS;
    const int qn = qt * QT + r;
    *(float4*)&g_o[(b * NSEQ + qn) * DIM + head * HD + g * 4] = o;
}

// ---------------- launch ---------------------------------------------------
extern "C" void kernel_launch(void* const* d_in, const int* in_sizes, int n_in,
                              void* d_out, int out_size)
{
    const float* x      = (const float*)d_in[0];
    const float* qkv_w  = (const float*)d_in[1];
    const float* qkv_b  = (const float*)d_in[2];
    const float* proj_w = (const float*)d_in[3];
    const float* proj_b = (const float*)d_in[4];
    const float* rph    = (const float*)d_in[5];
    const float* rpw    = (const float*)d_in[6];
    float* out = (float*)d_out;

    cudaFuncSetAttribute(attn_kernel,
                         cudaFuncAttributeMaxDynamicSharedMemorySize,
                         ATTN_SMEM_BYTES);

    // 1) QKV projection: (8192,768) @ (768,2304) -> scatter to q/k/v
    sgemm_kernel<1><<<dim3(2304 / 128, 8192 / 64), 256>>>(
        x, qkv_w, qkv_b, nullptr, BROWS, 3 * DIM, DIM);

    // 2) decomposed relative position bias
    rel_kernel<<<dim3(BHT, 32), 256>>>(rph, rpw);

    // 3) fused attention (scores + softmax + PV)
    attn_kernel<<<dim3(NSEQ / QT, BHT), 256, ATTN_SMEM_BYTES>>>();

    // 4) output projection: (8192,768) @ (768,768) + bias -> d_out
    sgemm_kernel<0><<<dim3(DIM / 128, 8192 / 64), 256>>>(
        nullptr, proj_w, proj_b, out, BROWS, DIM, DIM);
}

// round 3
// speedup vs baseline: 2.6173x; 2.6173x over previous
#include <cuda_runtime.h>

#define NHEADS 12
#define HD 64
#define BHT 96        // B * NHEADS
#define NSEQ 1024     // H*W
#define DIM 768
#define BROWS 8192    // B * NSEQ

// ---------------- scratch (device globals; no allocation) ----------------
__device__ float g_q[BHT * NSEQ * HD];
__device__ float g_k[BHT * NSEQ * HD];
__device__ float g_v[BHT * NSEQ * HD];
__device__ float g_relh[BHT * 32 * 32 * 32];
__device__ float g_relw[BHT * 32 * 32 * 32];
__device__ float g_o[BROWS * DIM];

// ---------------- tf32 helpers --------------------------------------------
__device__ __forceinline__ unsigned f2tf32(float x) {
    unsigned y;
    asm("cvt.rna.tf32.f32 %0, %1;" : "=r"(y) : "f"(x));
    return y;
}

// D += A(16x8) @ B(8x8), tf32 in, f32 acc. Standard m16n8k8 fragment layout.
__device__ __forceinline__ void mma_tf32(float* d,
                                         unsigned a0, unsigned a1, unsigned a2, unsigned a3,
                                         unsigned b0, unsigned b1)
{
    asm volatile(
        "mma.sync.aligned.m16n8k8.row.col.f32.tf32.tf32.f32 "
        "{%0,%1,%2,%3}, {%4,%5,%6,%7}, {%8,%9}, {%0,%1,%2,%3};"
        : "+f"(d[0]), "+f"(d[1]), "+f"(d[2]), "+f"(d[3])
        : "r"(a0), "r"(a1), "r"(a2), "r"(a3), "r"(b0), "r"(b1));
}

// ---------------- tf32 tensor-core GEMM -----------------------------------
// BM=128, BN=128, BK=16, 256 threads, warp grid 2(m) x 4(n), warp tile 64x32.
// MODE 1: A = Ain (x), epilogue scatters into g_q/g_k/g_v (qkv projection)
// MODE 0: A = g_o, epilogue writes C = A@B + bias (output projection)
template <int MODE>
__global__ void __launch_bounds__(256) mm_kernel(
    const float* __restrict__ Ain, const float* __restrict__ Bmat,
    const float* __restrict__ bias, float* __restrict__ C,
    int M, int N, int K)
{
    __shared__ unsigned As[128 * 20];   // [m][k], stride 20 (==4 mod 32)
    __shared__ unsigned Bs[16 * 136];   // [k][n], stride 136 (==8 mod 32)

    const float* A = (MODE == 0) ? (const float*)g_o : Ain;

    const int bm = blockIdx.y * 128;
    const int bn = blockIdx.x * 128;
    const int t  = threadIdx.x;
    const int w  = t >> 5;
    const int lane = t & 31;
    const int g  = lane >> 2;
    const int tg = lane & 3;
    const int wm = w >> 2;        // 0..1
    const int wn = w & 3;         // 0..3

    const int a_row = t >> 1;          // 0..127
    const int a_k   = (t & 1) * 8;     // 0 or 8
    const int b_k   = t >> 4;          // 0..15
    const int b_n   = (t & 15) * 8;    // 0..120

    float acc[4][4][4];
#pragma unroll
    for (int i = 0; i < 4; i++)
#pragma unroll
        for (int j = 0; j < 4; j++)
#pragma unroll
            for (int q = 0; q < 4; q++) acc[i][j][q] = 0.f;

    for (int k0 = 0; k0 < K; k0 += 16) {
        // load A 128x16, B 16x128, convert to tf32
        {
            const float* ap = &A[(bm + a_row) * K + k0 + a_k];
            float4 av0 = *(const float4*)ap;
            float4 av1 = *(const float4*)(ap + 4);
            unsigned* as = &As[a_row * 20 + a_k];
            as[0] = f2tf32(av0.x); as[1] = f2tf32(av0.y);
            as[2] = f2tf32(av0.z); as[3] = f2tf32(av0.w);
            as[4] = f2tf32(av1.x); as[5] = f2tf32(av1.y);
            as[6] = f2tf32(av1.z); as[7] = f2tf32(av1.w);

            const float* bp = &Bmat[(k0 + b_k) * N + bn + b_n];
            float4 bv0 = *(const float4*)bp;
            float4 bv1 = *(const float4*)(bp + 4);
            unsigned* bs = &Bs[b_k * 136 + b_n];
            bs[0] = f2tf32(bv0.x); bs[1] = f2tf32(bv0.y);
            bs[2] = f2tf32(bv0.z); bs[3] = f2tf32(bv0.w);
            bs[4] = f2tf32(bv1.x); bs[5] = f2tf32(bv1.y);
            bs[6] = f2tf32(bv1.z); bs[7] = f2tf32(bv1.w);
        }
        __syncthreads();

#pragma unroll
        for (int ks = 0; ks < 2; ks++) {
            unsigned af[4][4];
#pragma unroll
            for (int mt = 0; mt < 4; mt++) {
                int r = wm * 64 + mt * 16 + g;
                af[mt][0] = As[r * 20 + ks * 8 + tg];
                af[mt][1] = As[(r + 8) * 20 + ks * 8 + tg];
                af[mt][2] = As[r * 20 + ks * 8 + tg + 4];
                af[mt][3] = As[(r + 8) * 20 + ks * 8 + tg + 4];
            }
            unsigned bf[4][2];
#pragma unroll
            for (int nt = 0; nt < 4; nt++) {
                int c = wn * 32 + nt * 8 + g;
                bf[nt][0] = Bs[(ks * 8 + tg) * 136 + c];
                bf[nt][1] = Bs[(ks * 8 + tg + 4) * 136 + c];
            }
#pragma unroll
            for (int mt = 0; mt < 4; mt++)
#pragma unroll
                for (int nt = 0; nt < 4; nt++)
                    mma_tf32(acc[mt][nt], af[mt][0], af[mt][1], af[mt][2], af[mt][3],
                             bf[nt][0], bf[nt][1]);
        }
        __syncthreads();
    }

    // epilogue
#pragma unroll
    for (int mt = 0; mt < 4; mt++) {
#pragma unroll
        for (int nt = 0; nt < 4; nt++) {
            int row = bm + wm * 64 + mt * 16 + g;
            int col = bn + wn * 32 + nt * 8 + 2 * tg;
#pragma unroll
            for (int q = 0; q < 4; q++) {
                int r = row + (q >> 1) * 8;
                int c = col + (q & 1);
                float v = acc[mt][nt][q] + bias[c];
                if (MODE == 0) {
                    C[r * N + c] = v;
                } else {
                    const int b = r >> 10;
                    const int n = r & 1023;
                    const int which = c / 768;
                    const int rem = c - which * 768;
                    const int head = rem >> 6;
                    const int d = rem & 63;
                    float* dst = (which == 0) ? g_q : (which == 1) ? g_k : g_v;
                    dst[((b * NHEADS + head) * NSEQ + n) * HD + d] = v;
                }
            }
        }
    }
}

// ---------------- relative position bias: one block per (bh, qh) ----------
__global__ void __launch_bounds__(256) rel_kernel(
    const float* __restrict__ rph,   // (63, 64)
    const float* __restrict__ rpw)   // (63, 64)
{
    __shared__ float qrow[32 * 64];
    __shared__ float rh[32 * 65];
    __shared__ float rw[63 * 65];

    const int bh = blockIdx.x;
    const int qh = blockIdx.y;
    const int t  = threadIdx.x;

    for (int i = t; i < 32 * 64; i += 256) {
        int row = i >> 6, d = i & 63;
        qrow[i] = g_q[((bh * NSEQ) + qh * 32 + row) * HD + d];
        rh[row * 65 + d] = rph[(qh + row) * 64 + d];
    }
    for (int i = t; i < 63 * 64; i += 256) {
        int row = i >> 6, d = i & 63;
        rw[row * 65 + d] = rpw[i];
    }
    __syncthreads();

    for (int o = t; o < 2048; o += 256) {
        if (o < 1024) {
            int qw = o >> 5, kh = o & 31;
            const float* a  = &qrow[qw * 64];
            const float* b2 = &rh[(31 - kh) * 65];
            float s = 0.f;
#pragma unroll
            for (int d = 0; d < 64; d++) s += a[d] * b2[d];
            g_relh[(((bh * 32 + qh) * 32 + qw) * 32) + kh] = s;
        } else {
            int oo = o - 1024;
            int qw = oo >> 5, kw = oo & 31;
            const float* a  = &qrow[qw * 64];
            const float* b2 = &rw[(qw - kw + 31) * 65];
            float s = 0.f;
#pragma unroll
            for (int d = 0; d < 64; d++) s += a[d] * b2[d];
            g_relw[(((bh * 32 + qh) * 32 + qw) * 32) + kw] = s;
        }
    }
}

// ---------------- fused attention (tensor core): 32-query tile ------------
// smem float offsets
#define SM_QS     0                          // [32][68] tf32         = 2176
#define SM_RELH   2176                       // [32][32]              = 1024
#define SM_RELW   3200                       // [32][32]              = 1024
#define SM_SCORES 4224                       // [32][1028]            = 32896
#define SM_KV     37120                      // K:[128][68] / V:[128][72] = 9216
#define ATTN_SMEM_FLOATS (37120 + 128 * 72)
#define ATTN_SMEM_BYTES  (ATTN_SMEM_FLOATS * 4)

__global__ void __launch_bounds__(256, 1) attn_kernel()
{
    extern __shared__ float sm[];
    unsigned* qs    = (unsigned*)(sm + SM_QS);
    float* relh_s   = sm + SM_RELH;
    float* relw_s   = sm + SM_RELW;
    float* scores   = sm + SM_SCORES;
    unsigned* su    = (unsigned*)scores;
    unsigned* kvu   = (unsigned*)(sm + SM_KV);

    const int qt = blockIdx.x;   // 0..31 (32 q rows each)
    const int bh = blockIdx.y;   // 0..95
    const int t  = threadIdx.x;
    const int w  = t >> 5;
    const int lane = t & 31;
    const int g  = lane >> 2;
    const int tg = lane & 3;
    const float scale = 0.125f;

    // load Q tile (32x64) as tf32
    for (int i = t; i < 32 * 64; i += 256) {
        int r = i >> 6, d = i & 63;
        qs[r * 68 + d] = f2tf32(g_q[(bh * NSEQ + qt * 32 + r) * HD + d]);
    }
    // load rel bias rows for 32 q rows
    for (int i = t; i < 32 * 32; i += 256) {
        int r = i >> 5, c = i & 31;
        int qn = qt * 32 + r;
        int qh = qn >> 5, qw = qn & 31;
        int base = ((bh * 32 + qh) * 32 + qw) * 32 + c;
        relh_s[i] = g_relh[base];
        relw_s[i] = g_relw[base];
    }
    __syncthreads();

    // preload Q fragments: 2 m-tiles x 8 k-steps x 4 regs
    unsigned qf[2][8][4];
#pragma unroll
    for (int mt = 0; mt < 2; mt++)
#pragma unroll
        for (int ks = 0; ks < 8; ks++) {
            int row = mt * 16 + g;
            int col = ks * 8 + tg;
            qf[mt][ks][0] = qs[row * 68 + col];
            qf[mt][ks][1] = qs[(row + 8) * 68 + col];
            qf[mt][ks][2] = qs[row * 68 + col + 4];
            qf[mt][ks][3] = qs[(row + 8) * 68 + col + 4];
        }

    // ---------- score phase: tiles of 128 keys -----------------------------
    for (int kt = 0; kt < 8; kt++) {
        __syncthreads();
#pragma unroll
        for (int f = 0; f < 8; f++) {
            int fi = t + 256 * f;
            int row = fi >> 4;
            int col = (fi & 15) * 4;
            float4 kv4 = *(const float4*)&g_k[(bh * NSEQ + kt * 128 + row) * HD + col];
            uint4 u;
            u.x = f2tf32(kv4.x); u.y = f2tf32(kv4.y);
            u.z = f2tf32(kv4.z); u.w = f2tf32(kv4.w);
            *(uint4*)&kvu[row * 68 + col] = u;
        }
        __syncthreads();

        float acc[2][2][4];
#pragma unroll
        for (int i = 0; i < 2; i++)
#pragma unroll
            for (int j = 0; j < 2; j++)
#pragma unroll
                for (int q = 0; q < 4; q++) acc[i][j][q] = 0.f;

#pragma unroll
        for (int ks = 0; ks < 8; ks++) {
            unsigned bf[2][2];
#pragma unroll
            for (int nt = 0; nt < 2; nt++) {
                int key = w * 16 + nt * 8 + g;
                bf[nt][0] = kvu[key * 68 + ks * 8 + tg];
                bf[nt][1] = kvu[key * 68 + ks * 8 + tg + 4];
            }
#pragma unroll
            for (int mt = 0; mt < 2; mt++)
#pragma unroll
                for (int nt = 0; nt < 2; nt++)
                    mma_tf32(acc[mt][nt], qf[mt][ks][0], qf[mt][ks][1],
                             qf[mt][ks][2], qf[mt][ks][3], bf[nt][0], bf[nt][1]);
        }

        // store scores with scale + decomposed rel bias
#pragma unroll
        for (int mt = 0; mt < 2; mt++)
#pragma unroll
            for (int nt = 0; nt < 2; nt++) {
                int r = mt * 16 + g;
                int c = kt * 128 + w * 16 + nt * 8 + 2 * tg;
#pragma unroll
                for (int q = 0; q < 4; q++) {
                    int rr = r + (q >> 1) * 8;
                    int cc = c + (q & 1);
                    int kh = cc >> 5, kw = cc & 31;
                    scores[rr * 1028 + cc] =
                        acc[mt][nt][q] * scale + relh_s[rr * 32 + kh] + relw_s[rr * 32 + kw];
                }
            }
    }
    __syncthreads();

    // ---------- softmax: half-warp per row, 2 rows each ---------------------
    {
        const int hw = t >> 4;
        const int l16 = t & 15;
#pragma unroll
        for (int rr = 0; rr < 2; rr++) {
            int row = hw + rr * 16;
            float* srow = scores + row * 1028;
            float m = -1e30f;
#pragma unroll 8
            for (int i = 0; i < 64; i++)
                m = fmaxf(m, srow[l16 + i * 16]);
#pragma unroll
            for (int off = 8; off; off >>= 1)
                m = fmaxf(m, __shfl_xor_sync(0xffffffffu, m, off));
            float sum = 0.f;
#pragma unroll 8
            for (int i = 0; i < 64; i++) {
                float e = __expf(srow[l16 + i * 16] - m);
                srow[l16 + i * 16] = e;
                sum += e;
            }
#pragma unroll
            for (int off = 8; off; off >>= 1)
                sum += __shfl_xor_sync(0xffffffffu, sum, off);
            float inv = 1.0f / sum;
#pragma unroll 8
            for (int i = 0; i < 64; i++)
                srow[l16 + i * 16] = __uint_as_float(f2tf32(srow[l16 + i * 16] * inv));
        }
    }

    // ---------- PV phase: O = P @ V -----------------------------------------
    float po[2][4];
#pragma unroll
    for (int i = 0; i < 2; i++)
#pragma unroll
        for (int q = 0; q < 4; q++) po[i][q] = 0.f;

    for (int vt = 0; vt < 8; vt++) {
        __syncthreads();
#pragma unroll
        for (int f = 0; f < 8; f++) {
            int fi = t + 256 * f;
            int row = fi >> 4;
            int col = (fi & 15) * 4;
            float4 v4 = *(const float4*)&g_v[(bh * NSEQ + vt * 128 + row) * HD + col];
            uint4 u;
            u.x = f2tf32(v4.x); u.y = f2tf32(v4.y);
            u.z = f2tf32(v4.z); u.w = f2tf32(v4.w);
            *(uint4*)&kvu[row * 72 + col] = u;
        }
        __syncthreads();

#pragma unroll
        for (int ks = 0; ks < 16; ks++) {
            unsigned b0 = kvu[(ks * 8 + tg) * 72 + w * 8 + g];
            unsigned b1 = kvu[(ks * 8 + tg + 4) * 72 + w * 8 + g];
#pragma unroll
            for (int mt = 0; mt < 2; mt++) {
                int base = (mt * 16 + g) * 1028 + vt * 128 + ks * 8 + tg;
                unsigned a0 = su[base];
                unsigned a1 = su[base + 8 * 1028];
                unsigned a2 = su[base + 4];
                unsigned a3 = su[base + 8 * 1028 + 4];
                mma_tf32(po[mt], a0, a1, a2, a3, b0, b1);
            }
        }
    }

    // write to g_o [b][n][head][d]
    const int b = bh / NHEADS;
    const int head = bh % NHEADS;
#pragma unroll
    for (int mt = 0; mt < 2; mt++) {
        int m0 = qt * 32 + mt * 16 + g;
        int cb = head * HD + w * 8 + 2 * tg;
        g_o[(b * NSEQ + m0) * DIM + cb]         = po[mt][0];
        g_o[(b * NSEQ + m0) * DIM + cb + 1]     = po[mt][1];
        g_o[(b * NSEQ + m0 + 8) * DIM + cb]     = po[mt][2];
        g_o[(b * NSEQ + m0 + 8) * DIM + cb + 1] = po[mt][3];
    }
}

// ---------------- launch ---------------------------------------------------
extern "C" void kernel_launch(void* const* d_in, const int* in_sizes, int n_in,
                              void* d_out, int out_size)
{
    const float* x      = (const float*)d_in[0];
    const float* qkv_w  = (const float*)d_in[1];
    const float* qkv_b  = (const float*)d_in[2];
    const float* proj_w = (const float*)d_in[3];
    const float* proj_b = (const float*)d_in[4];
    const float* rph    = (const float*)d_in[5];
    const float* rpw    = (const float*)d_in[6];
    float* out = (float*)d_out;

    cudaFuncSetAttribute(attn_kernel,
                         cudaFuncAttributeMaxDynamicSharedMemorySize,
                         ATTN_SMEM_BYTES);

    // 1) QKV projection: (8192,768) @ (768,2304) -> scatter to q/k/v
    mm_kernel<1><<<dim3(2304 / 128, 8192 / 128), 256>>>(
        x, qkv_w, qkv_b, nullptr, BROWS, 3 * DIM, DIM);

    // 2) decomposed relative position bias
    rel_kernel<<<dim3(BHT, 32), 256>>>(rph, rpw);

    // 3) fused attention (scores + softmax + PV), 32-query tiles
    attn_kernel<<<dim3(NSEQ / 32, BHT), 256, ATTN_SMEM_BYTES>>>();

    // 4) output projection: (8192,768) @ (768,768) + bias -> d_out
    mm_kernel<0><<<dim3(DIM / 128, 8192 / 128), 256>>>(
        nullptr, proj_w, proj_b, out, BROWS, DIM, DIM);
}

// round 4
// speedup vs baseline: 3.0774x; 1.1758x over previous
#include <cuda_runtime.h>

#define NHEADS 12
#define HD 64
#define BHT 96        // B * NHEADS
#define NSEQ 1024     // H*W
#define DIM 768
#define BROWS 8192    // B * NSEQ

// ---------------- scratch (device globals; no allocation) ----------------
__device__ float g_q[BHT * NSEQ * HD];   // tf32-rounded bits
__device__ float g_k[BHT * NSEQ * HD];   // tf32-rounded bits
__device__ float g_v[BHT * NSEQ * HD];   // tf32-rounded bits
__device__ float g_relh[BHT * 32 * 32 * 32];
__device__ float g_relw[BHT * 32 * 32 * 32];
__device__ float g_o[BROWS * DIM];

// ---------------- tf32 helpers --------------------------------------------
__device__ __forceinline__ unsigned f2tf32(float x) {
    unsigned y;
    asm("cvt.rna.tf32.f32 %0, %1;" : "=r"(y) : "f"(x));
    return y;
}

// D += A(16x8) @ B(8x8), tf32 in, f32 acc. m16n8k8 fragment layout.
__device__ __forceinline__ void mma_tf32(float* d,
                                         unsigned a0, unsigned a1, unsigned a2, unsigned a3,
                                         unsigned b0, unsigned b1)
{
    asm volatile(
        "mma.sync.aligned.m16n8k8.row.col.f32.tf32.tf32.f32 "
        "{%0,%1,%2,%3}, {%4,%5,%6,%7}, {%8,%9}, {%0,%1,%2,%3};"
        : "+f"(d[0]), "+f"(d[1]), "+f"(d[2]), "+f"(d[3])
        : "r"(a0), "r"(a1), "r"(a2), "r"(a3), "r"(b0), "r"(b1));
}

// ---------------- tf32 tensor-core GEMM, double buffered -------------------
// BM=128, BN=128, BK=16, 256 threads, warp grid 2(m) x 4(n), warp tile 64x32.
// MODE 1: A = Ain (x), epilogue scatters tf32-rounded values into g_q/g_k/g_v
// MODE 0: A = g_o, epilogue writes C = A@B + bias
template <int MODE>
__global__ void __launch_bounds__(256, 2) mm_kernel(
    const float* __restrict__ Ain, const float* __restrict__ Bmat,
    const float* __restrict__ bias, float* __restrict__ C,
    int M, int N, int K)
{
    __shared__ unsigned As[2][128 * 20];   // [m][k], stride 20
    __shared__ unsigned Bs[2][16 * 136];   // [k][n], stride 136

    const float* A = (MODE == 0) ? (const float*)g_o : Ain;

    const int bm = blockIdx.y * 128;
    const int bn = blockIdx.x * 128;
    const int t  = threadIdx.x;
    const int w  = t >> 5;
    const int lane = t & 31;
    const int g  = lane >> 2;
    const int tg = lane & 3;
    const int wm = w >> 2;        // 0..1
    const int wn = w & 3;         // 0..3

    const int a_row = t >> 1;          // 0..127
    const int a_k   = (t & 1) * 8;     // 0 or 8
    const int b_k   = t >> 4;          // 0..15
    const int b_n   = (t & 15) * 8;    // 0..120

    float acc[4][4][4];
#pragma unroll
    for (int i = 0; i < 4; i++)
#pragma unroll
        for (int j = 0; j < 4; j++)
#pragma unroll
            for (int q = 0; q < 4; q++) acc[i][j][q] = 0.f;

    const int nk = K / 16;
    float4 ar0, ar1, br0, br1;

    // prologue: load + store tile 0
    {
        const float* ap = &A[(bm + a_row) * K + a_k];
        ar0 = *(const float4*)ap; ar1 = *(const float4*)(ap + 4);
        const float* bp = &Bmat[b_k * N + bn + b_n];
        br0 = *(const float4*)bp; br1 = *(const float4*)(bp + 4);
        unsigned* as = &As[0][a_row * 20 + a_k];
        as[0] = f2tf32(ar0.x); as[1] = f2tf32(ar0.y);
        as[2] = f2tf32(ar0.z); as[3] = f2tf32(ar0.w);
        as[4] = f2tf32(ar1.x); as[5] = f2tf32(ar1.y);
        as[6] = f2tf32(ar1.z); as[7] = f2tf32(ar1.w);
        unsigned* bs = &Bs[0][b_k * 136 + b_n];
        bs[0] = f2tf32(br0.x); bs[1] = f2tf32(br0.y);
        bs[2] = f2tf32(br0.z); bs[3] = f2tf32(br0.w);
        bs[4] = f2tf32(br1.x); bs[5] = f2tf32(br1.y);
        bs[6] = f2tf32(br1.z); bs[7] = f2tf32(br1.w);
    }
    __syncthreads();

    for (int kt = 0; kt < nk; kt++) {
        const int cur = kt & 1;
        // prefetch next tile into registers (overlaps with MMA below)
        if (kt + 1 < nk) {
            const float* ap = &A[(bm + a_row) * K + (kt + 1) * 16 + a_k];
            ar0 = *(const float4*)ap; ar1 = *(const float4*)(ap + 4);
            const float* bp = &Bmat[((kt + 1) * 16 + b_k) * N + bn + b_n];
            br0 = *(const float4*)bp; br1 = *(const float4*)(bp + 4);
        }

#pragma unroll
        for (int ks = 0; ks < 2; ks++) {
            unsigned af[4][4];
#pragma unroll
            for (int mt = 0; mt < 4; mt++) {
                int r = wm * 64 + mt * 16 + g;
                af[mt][0] = As[cur][r * 20 + ks * 8 + tg];
                af[mt][1] = As[cur][(r + 8) * 20 + ks * 8 + tg];
                af[mt][2] = As[cur][r * 20 + ks * 8 + tg + 4];
                af[mt][3] = As[cur][(r + 8) * 20 + ks * 8 + tg + 4];
            }
            unsigned bf[4][2];
#pragma unroll
            for (int nt = 0; nt < 4; nt++) {
                int c = wn * 32 + nt * 8 + g;
                bf[nt][0] = Bs[cur][(ks * 8 + tg) * 136 + c];
                bf[nt][1] = Bs[cur][(ks * 8 + tg + 4) * 136 + c];
            }
#pragma unroll
            for (int mt = 0; mt < 4; mt++)
#pragma unroll
                for (int nt = 0; nt < 4; nt++)
                    mma_tf32(acc[mt][nt], af[mt][0], af[mt][1], af[mt][2], af[mt][3],
                             bf[nt][0], bf[nt][1]);
        }

        if (kt + 1 < nk) {
            const int nxt = 1 - cur;
            unsigned* as = &As[nxt][a_row * 20 + a_k];
            as[0] = f2tf32(ar0.x); as[1] = f2tf32(ar0.y);
            as[2] = f2tf32(ar0.z); as[3] = f2tf32(ar0.w);
            as[4] = f2tf32(ar1.x); as[5] = f2tf32(ar1.y);
            as[6] = f2tf32(ar1.z); as[7] = f2tf32(ar1.w);
            unsigned* bs = &Bs[nxt][b_k * 136 + b_n];
            bs[0] = f2tf32(br0.x); bs[1] = f2tf32(br0.y);
            bs[2] = f2tf32(br0.z); bs[3] = f2tf32(br0.w);
            bs[4] = f2tf32(br1.x); bs[5] = f2tf32(br1.y);
            bs[6] = f2tf32(br1.z); bs[7] = f2tf32(br1.w);
            __syncthreads();
        }
    }

    // epilogue
#pragma unroll
    for (int mt = 0; mt < 4; mt++) {
#pragma unroll
        for (int nt = 0; nt < 4; nt++) {
            int row = bm + wm * 64 + mt * 16 + g;
            int col = bn + wn * 32 + nt * 8 + 2 * tg;
#pragma unroll
            for (int q = 0; q < 4; q++) {
                int r = row + (q >> 1) * 8;
                int c = col + (q & 1);
                float v = acc[mt][nt][q] + bias[c];
                if (MODE == 0) {
                    C[r * N + c] = v;
                } else {
                    const int b = r >> 10;
                    const int n = r & 1023;
                    const int which = c / 768;
                    const int rem = c - which * 768;
                    const int head = rem >> 6;
                    const int d = rem & 63;
                    float* dst = (which == 0) ? g_q : (which == 1) ? g_k : g_v;
                    // store tf32-rounded bits so downstream kernels skip cvt
                    dst[((b * NHEADS + head) * NSEQ + n) * HD + d] =
                        __uint_as_float(f2tf32(v));
                }
            }
        }
    }
}

// ---------------- relative position bias: one block per (bh, qh) ----------
__global__ void __launch_bounds__(256) rel_kernel(
    const float* __restrict__ rph,   // (63, 64)
    const float* __restrict__ rpw)   // (63, 64)
{
    __shared__ float qrow[32 * 64];
    __shared__ float rh[32 * 65];
    __shared__ float rw[63 * 65];

    const int bh = blockIdx.x;
    const int qh = blockIdx.y;
    const int t  = threadIdx.x;

    for (int i = t; i < 32 * 64; i += 256) {
        int row = i >> 6, d = i & 63;
        qrow[i] = g_q[((bh * NSEQ) + qh * 32 + row) * HD + d];
        rh[row * 65 + d] = rph[(qh + row) * 64 + d];
    }
    for (int i = t; i < 63 * 64; i += 256) {
        int row = i >> 6, d = i & 63;
        rw[row * 65 + d] = rpw[i];
    }
    __syncthreads();

    for (int o = t; o < 2048; o += 256) {
        if (o < 1024) {
            int qw = o >> 5, kh = o & 31;
            const float* a  = &qrow[qw * 64];
            const float* b2 = &rh[(31 - kh) * 65];
            float s = 0.f;
#pragma unroll
            for (int d = 0; d < 64; d++) s += a[d] * b2[d];
            g_relh[(((bh * 32 + qh) * 32 + qw) * 32) + kh] = s;
        } else {
            int oo = o - 1024;
            int qw = oo >> 5, kw = oo & 31;
            const float* a  = &qrow[qw * 64];
            const float* b2 = &rw[(qw - kw + 31) * 65];
            float s = 0.f;
#pragma unroll
            for (int d = 0; d < 64; d++) s += a[d] * b2[d];
            g_relw[(((bh * 32 + qh) * 32 + qw) * 32) + kw] = s;
        }
    }
}

// ---------------- fused attention (tensor core): 32-query tile ------------
// smem float offsets
#define SM_QS     0                          // [32][68] tf32 bits    = 2176
#define SM_RELH   2176                       // [32][32]              = 1024
#define SM_RELW   3200                       // [32][32]              = 1024
#define SM_SSUM   4224                       // [32] row inv-sums     = 32
#define SM_SCORES 4256                       // [32][1028]            = 32896
#define SM_KV     37152                      // K:[128][68] / V:[128][72]
#define ATTN_SMEM_FLOATS (37152 + 128 * 72)
#define ATTN_SMEM_BYTES  (ATTN_SMEM_FLOATS * 4)

__global__ void __launch_bounds__(256, 1) attn_kernel()
{
    extern __shared__ float sm[];
    unsigned* qs    = (unsigned*)(sm + SM_QS);
    float* relh_s   = sm + SM_RELH;
    float* relw_s   = sm + SM_RELW;
    float* ssum     = sm + SM_SSUM;
    float* scores   = sm + SM_SCORES;
    unsigned* su    = (unsigned*)scores;
    unsigned* kvu   = (unsigned*)(sm + SM_KV);

    const int qt = blockIdx.x;   // 0..31 (32 q rows each)
    const int bh = blockIdx.y;   // 0..95
    const int t  = threadIdx.x;
    const int w  = t >> 5;
    const int lane = t & 31;
    const int g  = lane >> 2;
    const int tg = lane & 3;
    const float scale = 0.125f;

    // load Q tile (32x64, already tf32 bits) — vectorized copy
#pragma unroll
    for (int f = 0; f < 2; f++) {
        int i = t + 256 * f;          // float4 index over 32x64
        int r = i >> 4;
        int c = (i & 15) * 4;
        *(uint4*)&qs[r * 68 + c] =
            *(const uint4*)&g_q[(bh * NSEQ + qt * 32 + r) * HD + c];
    }
    // load rel bias rows for 32 q rows
    for (int i = t; i < 32 * 32; i += 256) {
        int r = i >> 5, c = i & 31;
        int qn = qt * 32 + r;
        int qh = qn >> 5, qw = qn & 31;
        int base = ((bh * 32 + qh) * 32 + qw) * 32 + c;
        relh_s[i] = g_relh[base];
        relw_s[i] = g_relw[base];
    }
    __syncthreads();

    // preload Q fragments: 2 m-tiles x 8 k-steps x 4 regs
    unsigned qf[2][8][4];
#pragma unroll
    for (int mt = 0; mt < 2; mt++)
#pragma unroll
        for (int ks = 0; ks < 8; ks++) {
            int row = mt * 16 + g;
            int col = ks * 8 + tg;
            qf[mt][ks][0] = qs[row * 68 + col];
            qf[mt][ks][1] = qs[(row + 8) * 68 + col];
            qf[mt][ks][2] = qs[row * 68 + col + 4];
            qf[mt][ks][3] = qs[(row + 8) * 68 + col + 4];
        }

    // ---------- score phase: tiles of 128 keys, register-staged prefetch ---
    uint4 kst[8];
#pragma unroll
    for (int f = 0; f < 8; f++) {
        int fi = t + 256 * f;
        int row = fi >> 4;
        int col = (fi & 15) * 4;
        kst[f] = *(const uint4*)&g_k[(bh * NSEQ + row) * HD + col];
    }

    for (int kt = 0; kt < 8; kt++) {
        __syncthreads();   // previous consumers of kvu done
#pragma unroll
        for (int f = 0; f < 8; f++) {
            int fi = t + 256 * f;
            int row = fi >> 4;
            int col = (fi & 15) * 4;
            *(uint4*)&kvu[row * 68 + col] = kst[f];
        }
        __syncthreads();   // tile ready
        if (kt + 1 < 8) {
#pragma unroll
            for (int f = 0; f < 8; f++) {
                int fi = t + 256 * f;
                int row = fi >> 4;
                int col = (fi & 15) * 4;
                kst[f] = *(const uint4*)&g_k[(bh * NSEQ + (kt + 1) * 128 + row) * HD + col];
            }
        }

        float acc[2][2][4];
#pragma unroll
        for (int i = 0; i < 2; i++)
#pragma unroll
            for (int j = 0; j < 2; j++)
#pragma unroll
                for (int q = 0; q < 4; q++) acc[i][j][q] = 0.f;

#pragma unroll
        for (int ks = 0; ks < 8; ks++) {
            unsigned bf[2][2];
#pragma unroll
            for (int nt = 0; nt < 2; nt++) {
                int key = w * 16 + nt * 8 + g;
                bf[nt][0] = kvu[key * 68 + ks * 8 + tg];
                bf[nt][1] = kvu[key * 68 + ks * 8 + tg + 4];
            }
#pragma unroll
            for (int mt = 0; mt < 2; mt++)
#pragma unroll
                for (int nt = 0; nt < 2; nt++)
                    mma_tf32(acc[mt][nt], qf[mt][ks][0], qf[mt][ks][1],
                             qf[mt][ks][2], qf[mt][ks][3], bf[nt][0], bf[nt][1]);
        }

        // store scores with scale + decomposed rel bias
#pragma unroll
        for (int mt = 0; mt < 2; mt++)
#pragma unroll
            for (int nt = 0; nt < 2; nt++) {
                int r = mt * 16 + g;
                int c = kt * 128 + w * 16 + nt * 8 + 2 * tg;
#pragma unroll
                for (int q = 0; q < 4; q++) {
                    int rr = r + (q >> 1) * 8;
                    int cc = c + (q & 1);
                    int kh = cc >> 5, kw = cc & 31;
                    scores[rr * 1028 + cc] =
                        acc[mt][nt][q] * scale + relh_s[rr * 32 + kh] + relw_s[rr * 32 + kw];
                }
            }
    }
    __syncthreads();

    // ---------- softmax (no normalize pass; divide in PV epilogue) ---------
    {
        const int hw = t >> 4;
        const int l16 = t & 15;
#pragma unroll
        for (int rr = 0; rr < 2; rr++) {
            int row = hw + rr * 16;
            float* srow = scores + row * 1028;
            float m = -1e30f;
#pragma unroll 8
            for (int i = 0; i < 64; i++)
                m = fmaxf(m, srow[l16 + i * 16]);
#pragma unroll
            for (int off = 8; off; off >>= 1)
                m = fmaxf(m, __shfl_xor_sync(0xffffffffu, m, off));
            float sum = 0.f;
#pragma unroll 8
            for (int i = 0; i < 64; i++) {
                float e = __expf(srow[l16 + i * 16] - m);
                srow[l16 + i * 16] = e;
                sum += e;
            }
#pragma unroll
            for (int off = 8; off; off >>= 1)
                sum += __shfl_xor_sync(0xffffffffu, sum, off);
            if (l16 == 0) ssum[row] = 1.0f / sum;
        }
    }

    // ---------- PV phase: O = P @ V, register-staged prefetch --------------
    float po[2][4];
#pragma unroll
    for (int i = 0; i < 2; i++)
#pragma unroll
        for (int q = 0; q < 4; q++) po[i][q] = 0.f;

    uint4 vst[8];
#pragma unroll
    for (int f = 0; f < 8; f++) {
        int fi = t + 256 * f;
        int row = fi >> 4;
        int col = (fi & 15) * 4;
        vst[f] = *(const uint4*)&g_v[(bh * NSEQ + row) * HD + col];
    }

    for (int vt = 0; vt < 8; vt++) {
        __syncthreads();
#pragma unroll
        for (int f = 0; f < 8; f++) {
            int fi = t + 256 * f;
            int row = fi >> 4;
            int col = (fi & 15) * 4;
            *(uint4*)&kvu[row * 72 + col] = vst[f];
        }
        __syncthreads();
        if (vt + 1 < 8) {
#pragma unroll
            for (int f = 0; f < 8; f++) {
                int fi = t + 256 * f;
                int row = fi >> 4;
                int col = (fi & 15) * 4;
                vst[f] = *(const uint4*)&g_v[(bh * NSEQ + (vt + 1) * 128 + row) * HD + col];
            }
        }

#pragma unroll
        for (int ks = 0; ks < 16; ks++) {
            unsigned b0 = kvu[(ks * 8 + tg) * 72 + w * 8 + g];
            unsigned b1 = kvu[(ks * 8 + tg + 4) * 72 + w * 8 + g];
#pragma unroll
            for (int mt = 0; mt < 2; mt++) {
                int base = (mt * 16 + g) * 1028 + vt * 128 + ks * 8 + tg;
                unsigned a0 = su[base];
                unsigned a1 = su[base + 8 * 1028];
                unsigned a2 = su[base + 4];
                unsigned a3 = su[base + 8 * 1028 + 4];
                mma_tf32(po[mt], a0, a1, a2, a3, b0, b1);
            }
        }
    }

    // write to g_o [b][n][head][d], applying 1/rowsum
    const int b = bh / NHEADS;
    const int head = bh % NHEADS;
#pragma unroll
    for (int mt = 0; mt < 2; mt++) {
        int m0 = qt * 32 + mt * 16 + g;
        int cb = head * HD + w * 8 + 2 * tg;
        float i0 = ssum[mt * 16 + g];
        float i1 = ssum[mt * 16 + g + 8];
        g_o[(b * NSEQ + m0) * DIM + cb]         = po[mt][0] * i0;
        g_o[(b * NSEQ + m0) * DIM + cb + 1]     = po[mt][1] * i0;
        g_o[(b * NSEQ + m0 + 8) * DIM + cb]     = po[mt][2] * i1;
        g_o[(b * NSEQ + m0 + 8) * DIM + cb + 1] = po[mt][3] * i1;
    }
}

// ---------------- launch ---------------------------------------------------
extern "C" void kernel_launch(void* const* d_in, const int* in_sizes, int n_in,
                              void* d_out, int out_size)
{
    const float* x      = (const float*)d_in[0];
    const float* qkv_w  = (const float*)d_in[1];
    const float* qkv_b  = (const float*)d_in[2];
    const float* proj_w = (const float*)d_in[3];
    const float* proj_b = (const float*)d_in[4];
    const float* rph    = (const float*)d_in[5];
    const float* rpw    = (const float*)d_in[6];
    float* out = (float*)d_out;

    cudaFuncSetAttribute(attn_kernel,
                         cudaFuncAttributeMaxDynamicSharedMemorySize,
                         ATTN_SMEM_BYTES);

    // 1) QKV projection: (8192,768) @ (768,2304) -> scatter to q/k/v (tf32)
    mm_kernel<1><<<dim3(2304 / 128, 8192 / 128), 256>>>(
        x, qkv_w, qkv_b, nullptr, BROWS, 3 * DIM, DIM);

    // 2) decomposed relative position bias
    rel_kernel<<<dim3(BHT, 32), 256>>>(rph, rpw);

    // 3) fused attention (scores + softmax + PV), 32-query tiles
    attn_kernel<<<dim3(NSEQ / 32, BHT), 256, ATTN_SMEM_BYTES>>>();

    // 4) output projection: (8192,768) @ (768,768) + bias -> d_out
    mm_kernel<0><<<dim3(DIM / 128, 8192 / 128), 256>>>(
        nullptr, proj_w, proj_b, out, BROWS, DIM, DIM);
}

// round 5
// speedup vs baseline: 3.2530x; 1.0571x over previous
#include <cuda_runtime.h>

#define NHEADS 12
#define HD 64
#define BHT 96        // B * NHEADS
#define NSEQ 1024     // H*W
#define DIM 768
#define BROWS 8192    // B * NSEQ

// ---------------- scratch (device globals; no allocation) ----------------
__device__ float g_q[BHT * NSEQ * HD];   // tf32-rounded bits
__device__ float g_k[BHT * NSEQ * HD];   // tf32-rounded bits
__device__ float g_v[BHT * NSEQ * HD];   // tf32-rounded bits
__device__ float g_relh[BHT * 32 * 32 * 32];
__device__ float g_relw[BHT * 32 * 32 * 32];
__device__ float g_o[BROWS * DIM];

// ---------------- tf32 helpers --------------------------------------------
__device__ __forceinline__ unsigned f2tf32(float x) {
    unsigned y;
    asm("cvt.rna.tf32.f32 %0, %1;" : "=r"(y) : "f"(x));
    return y;
}

// D += A(16x8) @ B(8x8), tf32 in, f32 acc. m16n8k8 fragment layout.
__device__ __forceinline__ void mma_tf32(float* d,
                                         unsigned a0, unsigned a1, unsigned a2, unsigned a3,
                                         unsigned b0, unsigned b1)
{
    asm volatile(
        "mma.sync.aligned.m16n8k8.row.col.f32.tf32.tf32.f32 "
        "{%0,%1,%2,%3}, {%4,%5,%6,%7}, {%8,%9}, {%0,%1,%2,%3};"
        : "+f"(d[0]), "+f"(d[1]), "+f"(d[2]), "+f"(d[3])
        : "r"(a0), "r"(a1), "r"(a2), "r"(a3), "r"(b0), "r"(b1));
}

// ---------------- tf32 tensor-core GEMM, double buffered -------------------
// BM=128, BN=128, BK=16, 256 threads, warp grid 2(m) x 4(n), warp tile 64x32.
template <int MODE>
__global__ void __launch_bounds__(256, 2) mm_kernel(
    const float* __restrict__ Ain, const float* __restrict__ Bmat,
    const float* __restrict__ bias, float* __restrict__ C,
    int M, int N, int K)
{
    __shared__ unsigned As[2][128 * 20];
    __shared__ unsigned Bs[2][16 * 136];

    const float* A = (MODE == 0) ? (const float*)g_o : Ain;

    const int bm = blockIdx.y * 128;
    const int bn = blockIdx.x * 128;
    const int t  = threadIdx.x;
    const int w  = t >> 5;
    const int lane = t & 31;
    const int g  = lane >> 2;
    const int tg = lane & 3;
    const int wm = w >> 2;
    const int wn = w & 3;

    const int a_row = t >> 1;
    const int a_k   = (t & 1) * 8;
    const int b_k   = t >> 4;
    const int b_n   = (t & 15) * 8;

    float acc[4][4][4];
#pragma unroll
    for (int i = 0; i < 4; i++)
#pragma unroll
        for (int j = 0; j < 4; j++)
#pragma unroll
            for (int q = 0; q < 4; q++) acc[i][j][q] = 0.f;

    const int nk = K / 16;
    float4 ar0, ar1, br0, br1;

    {
        const float* ap = &A[(bm + a_row) * K + a_k];
        ar0 = *(const float4*)ap; ar1 = *(const float4*)(ap + 4);
        const float* bp = &Bmat[b_k * N + bn + b_n];
        br0 = *(const float4*)bp; br1 = *(const float4*)(bp + 4);
        unsigned* as = &As[0][a_row * 20 + a_k];
        as[0] = f2tf32(ar0.x); as[1] = f2tf32(ar0.y);
        as[2] = f2tf32(ar0.z); as[3] = f2tf32(ar0.w);
        as[4] = f2tf32(ar1.x); as[5] = f2tf32(ar1.y);
        as[6] = f2tf32(ar1.z); as[7] = f2tf32(ar1.w);
        unsigned* bs = &Bs[0][b_k * 136 + b_n];
        bs[0] = f2tf32(br0.x); bs[1] = f2tf32(br0.y);
        bs[2] = f2tf32(br0.z); bs[3] = f2tf32(br0.w);
        bs[4] = f2tf32(br1.x); bs[5] = f2tf32(br1.y);
        bs[6] = f2tf32(br1.z); bs[7] = f2tf32(br1.w);
    }
    __syncthreads();

    for (int kt = 0; kt < nk; kt++) {
        const int cur = kt & 1;
        if (kt + 1 < nk) {
            const float* ap = &A[(bm + a_row) * K + (kt + 1) * 16 + a_k];
            ar0 = *(const float4*)ap; ar1 = *(const float4*)(ap + 4);
            const float* bp = &Bmat[((kt + 1) * 16 + b_k) * N + bn + b_n];
            br0 = *(const float4*)bp; br1 = *(const float4*)(bp + 4);
        }

#pragma unroll
        for (int ks = 0; ks < 2; ks++) {
            unsigned af[4][4];
#pragma unroll
            for (int mt = 0; mt < 4; mt++) {
                int r = wm * 64 + mt * 16 + g;
                af[mt][0] = As[cur][r * 20 + ks * 8 + tg];
                af[mt][1] = As[cur][(r + 8) * 20 + ks * 8 + tg];
                af[mt][2] = As[cur][r * 20 + ks * 8 + tg + 4];
                af[mt][3] = As[cur][(r + 8) * 20 + ks * 8 + tg + 4];
            }
            unsigned bf[4][2];
#pragma unroll
            for (int nt = 0; nt < 4; nt++) {
                int c = wn * 32 + nt * 8 + g;
                bf[nt][0] = Bs[cur][(ks * 8 + tg) * 136 + c];
                bf[nt][1] = Bs[cur][(ks * 8 + tg + 4) * 136 + c];
            }
#pragma unroll
            for (int mt = 0; mt < 4; mt++)
#pragma unroll
                for (int nt = 0; nt < 4; nt++)
                    mma_tf32(acc[mt][nt], af[mt][0], af[mt][1], af[mt][2], af[mt][3],
                             bf[nt][0], bf[nt][1]);
        }

        if (kt + 1 < nk) {
            const int nxt = 1 - cur;
            unsigned* as = &As[nxt][a_row * 20 + a_k];
            as[0] = f2tf32(ar0.x); as[1] = f2tf32(ar0.y);
            as[2] = f2tf32(ar0.z); as[3] = f2tf32(ar0.w);
            as[4] = f2tf32(ar1.x); as[5] = f2tf32(ar1.y);
            as[6] = f2tf32(ar1.z); as[7] = f2tf32(ar1.w);
            unsigned* bs = &Bs[nxt][b_k * 136 + b_n];
            bs[0] = f2tf32(br0.x); bs[1] = f2tf32(br0.y);
            bs[2] = f2tf32(br0.z); bs[3] = f2tf32(br0.w);
            bs[4] = f2tf32(br1.x); bs[5] = f2tf32(br1.y);
            bs[6] = f2tf32(br1.z); bs[7] = f2tf32(br1.w);
            __syncthreads();
        }
    }

#pragma unroll
    for (int mt = 0; mt < 4; mt++) {
#pragma unroll
        for (int nt = 0; nt < 4; nt++) {
            int row = bm + wm * 64 + mt * 16 + g;
            int col = bn + wn * 32 + nt * 8 + 2 * tg;
#pragma unroll
            for (int q = 0; q < 4; q++) {
                int r = row + (q >> 1) * 8;
                int c = col + (q & 1);
                float v = acc[mt][nt][q] + bias[c];
                if (MODE == 0) {
                    C[r * N + c] = v;
                } else {
                    const int b = r >> 10;
                    const int n = r & 1023;
                    const int which = c / 768;
                    const int rem = c - which * 768;
                    const int head = rem >> 6;
                    const int d = rem & 63;
                    float* dst = (which == 0) ? g_q : (which == 1) ? g_k : g_v;
                    dst[((b * NHEADS + head) * NSEQ + n) * HD + d] =
                        __uint_as_float(f2tf32(v));
                }
            }
        }
    }
}

// ---------------- relative position bias: one block per (bh, qh) ----------
__global__ void __launch_bounds__(256) rel_kernel(
    const float* __restrict__ rph, const float* __restrict__ rpw)
{
    __shared__ float qrow[32 * 64];
    __shared__ float rh[32 * 65];
    __shared__ float rw[63 * 65];

    const int bh = blockIdx.x;
    const int qh = blockIdx.y;
    const int t  = threadIdx.x;

    for (int i = t; i < 32 * 64; i += 256) {
        int row = i >> 6, d = i & 63;
        qrow[i] = g_q[((bh * NSEQ) + qh * 32 + row) * HD + d];
        rh[row * 65 + d] = rph[(qh + row) * 64 + d];
    }
    for (int i = t; i < 63 * 64; i += 256) {
        int row = i >> 6, d = i & 63;
        rw[row * 65 + d] = rpw[i];
    }
    __syncthreads();

    for (int o = t; o < 2048; o += 256) {
        if (o < 1024) {
            int qw = o >> 5, kh = o & 31;
            const float* a  = &qrow[qw * 64];
            const float* b2 = &rh[(31 - kh) * 65];
            float s = 0.f;
#pragma unroll
            for (int d = 0; d < 64; d++) s += a[d] * b2[d];
            g_relh[(((bh * 32 + qh) * 32 + qw) * 32) + kh] = s;
        } else {
            int oo = o - 1024;
            int qw = oo >> 5, kw = oo & 31;
            const float* a  = &qrow[qw * 64];
            const float* b2 = &rw[(qw - kw + 31) * 65];
            float s = 0.f;
#pragma unroll
            for (int d = 0; d < 64; d++) s += a[d] * b2[d];
            g_relw[(((bh * 32 + qh) * 32 + qw) * 32) + kw] = s;
        }
    }
}

// ---------------- flash attention: online softmax, single K/V pass --------
// block = 32 q rows x full 1024 keys streamed in 128-key tiles. 256 threads.
// smem (floats):
#define SM_QS     0                        // [32][68]   = 2176
#define SM_RELH   2176                     // [32][32]   = 1024
#define SM_RELW   3200                     // [32][32]   = 1024
#define SM_PMAX   4224                     // [8][32]    = 256
#define SM_PSUM   4480                     // [8][32]    = 256
#define SM_P      4736                     // [32][132]  = 4224
#define SM_K      8960                     // [128][68]  = 8704
#define SM_V      17664                    // [128][72]  = 9216
#define ATTN_SMEM_FLOATS 26880             // 107,520 B
#define ATTN_SMEM_BYTES  (ATTN_SMEM_FLOATS * 4)

__global__ void __launch_bounds__(256, 2) attn_kernel()
{
    extern __shared__ float sm[];
    unsigned* qs  = (unsigned*)(sm + SM_QS);
    float* relh_s = sm + SM_RELH;
    float* relw_s = sm + SM_RELW;
    float* pmax   = sm + SM_PMAX;
    float* psum   = sm + SM_PSUM;
    unsigned* Pm  = (unsigned*)(sm + SM_P);
    unsigned* Km  = (unsigned*)(sm + SM_K);
    unsigned* Vm  = (unsigned*)(sm + SM_V);

    const int qt = blockIdx.x;   // 0..31
    const int bh = blockIdx.y;   // 0..95
    const int t  = threadIdx.x;
    const int w  = t >> 5;
    const int lane = t & 31;
    const int g  = lane >> 2;
    const int tg = lane & 3;
    const float scale = 0.125f;

    // load Q tile (32x64, tf32 bits)
#pragma unroll
    for (int f = 0; f < 2; f++) {
        int i = t + 256 * f;
        int r = i >> 4;
        int c = (i & 15) * 4;
        *(uint4*)&qs[r * 68 + c] =
            *(const uint4*)&g_q[(bh * NSEQ + qt * 32 + r) * HD + c];
    }
    // load rel bias rows
    for (int i = t; i < 32 * 32; i += 256) {
        int r = i >> 5, c = i & 31;
        int qn = qt * 32 + r;
        int qh = qn >> 5, qw = qn & 31;
        int base = ((bh * 32 + qh) * 32 + qw) * 32 + c;
        relh_s[i] = g_relh[base];
        relw_s[i] = g_relw[base];
    }
    __syncthreads();

    // preload Q fragments
    unsigned qf[2][8][4];
#pragma unroll
    for (int mt = 0; mt < 2; mt++)
#pragma unroll
        for (int ks = 0; ks < 8; ks++) {
            int row = mt * 16 + g;
            int col = ks * 8 + tg;
            qf[mt][ks][0] = qs[row * 68 + col];
            qf[mt][ks][1] = qs[(row + 8) * 68 + col];
            qf[mt][ks][2] = qs[row * 68 + col + 4];
            qf[mt][ks][3] = qs[(row + 8) * 68 + col + 4];
        }

    // online-softmax state. rows per thread: mt*16 + g + 8*rh
    float m_[2][2] = {{-1e30f, -1e30f}, {-1e30f, -1e30f}};
    float s_[2][2] = {{0.f, 0.f}, {0.f, 0.f}};
    float po[2][4] = {{0.f, 0.f, 0.f, 0.f}, {0.f, 0.f, 0.f, 0.f}};

    for (int kt = 0; kt < 8; kt++) {
        if (kt) __syncthreads();   // prev PV done reading K/V/P
        // load K,V tiles (tf32 bits, direct copy)
#pragma unroll
        for (int f = 0; f < 8; f++) {
            int fi = t + 256 * f;
            int row = fi >> 4;
            int col = (fi & 15) * 4;
            const float* src = &g_k[(bh * NSEQ + kt * 128 + row) * HD + col];
            *(uint4*)&Km[row * 68 + col] = *(const uint4*)src;
            *(uint4*)&Vm[row * 72 + col] =
                *(const uint4*)&g_v[(bh * NSEQ + kt * 128 + row) * HD + col];
        }
        __syncthreads();

        // ---- S = Q @ K^T (warp w owns keys w*16..w*16+15) ----
        float acc[2][2][4];
#pragma unroll
        for (int i = 0; i < 2; i++)
#pragma unroll
            for (int j = 0; j < 2; j++)
#pragma unroll
                for (int q = 0; q < 4; q++) acc[i][j][q] = 0.f;

#pragma unroll
        for (int ks = 0; ks < 8; ks++) {
            unsigned bf[2][2];
#pragma unroll
            for (int nt = 0; nt < 2; nt++) {
                int key = w * 16 + nt * 8 + g;
                bf[nt][0] = Km[key * 68 + ks * 8 + tg];
                bf[nt][1] = Km[key * 68 + ks * 8 + tg + 4];
            }
#pragma unroll
            for (int mt = 0; mt < 2; mt++)
#pragma unroll
                for (int nt = 0; nt < 2; nt++)
                    mma_tf32(acc[mt][nt], qf[mt][ks][0], qf[mt][ks][1],
                             qf[mt][ks][2], qf[mt][ks][3], bf[nt][0], bf[nt][1]);
        }

        // ---- scale + bias; per-(mt,rh) tile max over this warp's 16 cols --
        float tmax[2][2] = {{-1e30f, -1e30f}, {-1e30f, -1e30f}};
#pragma unroll
        for (int mt = 0; mt < 2; mt++)
#pragma unroll
            for (int nt = 0; nt < 2; nt++)
#pragma unroll
                for (int q = 0; q < 4; q++) {
                    int rr = mt * 16 + g + (q >> 1) * 8;
                    int cc = kt * 128 + w * 16 + nt * 8 + 2 * tg + (q & 1);
                    int kh = cc >> 5, kw = cc & 31;
                    float sv = acc[mt][nt][q] * scale
                             + relh_s[rr * 32 + kh] + relw_s[rr * 32 + kw];
                    acc[mt][nt][q] = sv;
                    tmax[mt][q >> 1] = fmaxf(tmax[mt][q >> 1], sv);
                }
#pragma unroll
        for (int mt = 0; mt < 2; mt++)
#pragma unroll
            for (int rh = 0; rh < 2; rh++) {
                float v = tmax[mt][rh];
                v = fmaxf(v, __shfl_xor_sync(0xffffffffu, v, 1));
                v = fmaxf(v, __shfl_xor_sync(0xffffffffu, v, 2));
                tmax[mt][rh] = v;
                if (tg == 0) pmax[w * 32 + mt * 16 + g + rh * 8] = v;
            }
        __syncthreads();

        // ---- m/alpha update, P = exp(S - m_new), partial sums -------------
        float alpha[2][2];
#pragma unroll
        for (int mt = 0; mt < 2; mt++)
#pragma unroll
            for (int rh = 0; rh < 2; rh++) {
                int row = mt * 16 + g + rh * 8;
                float mt_tile = pmax[row];
#pragma unroll
                for (int ww = 1; ww < 8; ww++)
                    mt_tile = fmaxf(mt_tile, pmax[ww * 32 + row]);
                float m_new = fmaxf(m_[mt][rh], mt_tile);
                alpha[mt][rh] = __expf(m_[mt][rh] - m_new);
                m_[mt][rh] = m_new;
            }

        float tsum[2][2] = {{0.f, 0.f}, {0.f, 0.f}};
#pragma unroll
        for (int mt = 0; mt < 2; mt++)
#pragma unroll
            for (int nt = 0; nt < 2; nt++)
#pragma unroll
                for (int q = 0; q < 4; q++) {
                    int rh = q >> 1;
                    int rr = mt * 16 + g + rh * 8;
                    int cl = w * 16 + nt * 8 + 2 * tg + (q & 1);
                    float e = __expf(acc[mt][nt][q] - m_[mt][rh]);
                    tsum[mt][rh] += e;
                    Pm[rr * 132 + cl] = f2tf32(e);
                }
#pragma unroll
        for (int mt = 0; mt < 2; mt++)
#pragma unroll
            for (int rh = 0; rh < 2; rh++) {
                float v = tsum[mt][rh];
                v += __shfl_xor_sync(0xffffffffu, v, 1);
                v += __shfl_xor_sync(0xffffffffu, v, 2);
                if (tg == 0) psum[w * 32 + mt * 16 + g + rh * 8] = v;
                // rescale O accumulator
                po[mt][rh * 2]     *= alpha[mt][rh];
                po[mt][rh * 2 + 1] *= alpha[mt][rh];
            }
        __syncthreads();

        // ---- s update ------------------------------------------------------
#pragma unroll
        for (int mt = 0; mt < 2; mt++)
#pragma unroll
            for (int rh = 0; rh < 2; rh++) {
                int row = mt * 16 + g + rh * 8;
                float ts = psum[row];
#pragma unroll
                for (int ww = 1; ww < 8; ww++)
                    ts += psum[ww * 32 + row];
                s_[mt][rh] = s_[mt][rh] * alpha[mt][rh] + ts;
            }

        // ---- PV: O += P @ V (warp w owns out dims w*8..w*8+7) ---------------
#pragma unroll
        for (int ks = 0; ks < 16; ks++) {
            unsigned b0 = Vm[(ks * 8 + tg) * 72 + w * 8 + g];
            unsigned b1 = Vm[(ks * 8 + tg + 4) * 72 + w * 8 + g];
#pragma unroll
            for (int mt = 0; mt < 2; mt++) {
                int base = (mt * 16 + g) * 132 + ks * 8 + tg;
                unsigned a0 = Pm[base];
                unsigned a1 = Pm[base + 8 * 132];
                unsigned a2 = Pm[base + 4];
                unsigned a3 = Pm[base + 8 * 132 + 4];
                mma_tf32(po[mt], a0, a1, a2, a3, b0, b1);
            }
        }
    }

    // ---- epilogue: normalize by row sums, write g_o [b][n][head][d] -------
    const int b = bh / NHEADS;
    const int head = bh % NHEADS;
#pragma unroll
    for (int mt = 0; mt < 2; mt++) {
        int m0 = qt * 32 + mt * 16 + g;
        int cb = head * HD + w * 8 + 2 * tg;
        float i0 = 1.0f / s_[mt][0];
        float i1 = 1.0f / s_[mt][1];
        g_o[(b * NSEQ + m0) * DIM + cb]         = po[mt][0] * i0;
        g_o[(b * NSEQ + m0) * DIM + cb + 1]     = po[mt][1] * i0;
        g_o[(b * NSEQ + m0 + 8) * DIM + cb]     = po[mt][2] * i1;
        g_o[(b * NSEQ + m0 + 8) * DIM + cb + 1] = po[mt][3] * i1;
    }
}

// ---------------- launch ---------------------------------------------------
extern "C" void kernel_launch(void* const* d_in, const int* in_sizes, int n_in,
                              void* d_out, int out_size)
{
    const float* x      = (const float*)d_in[0];
    const float* qkv_w  = (const float*)d_in[1];
    const float* qkv_b  = (const float*)d_in[2];
    const float* proj_w = (const float*)d_in[3];
    const float* proj_b = (const float*)d_in[4];
    const float* rph    = (const float*)d_in[5];
    const float* rpw    = (const float*)d_in[6];
    float* out = (float*)d_out;

    cudaFuncSetAttribute(attn_kernel,
                         cudaFuncAttributeMaxDynamicSharedMemorySize,
                         ATTN_SMEM_BYTES);

    // 1) QKV projection
    mm_kernel<1><<<dim3(2304 / 128, 8192 / 128), 256>>>(
        x, qkv_w, qkv_b, nullptr, BROWS, 3 * DIM, DIM);

    // 2) decomposed relative position bias
    rel_kernel<<<dim3(BHT, 32), 256>>>(rph, rpw);

    // 3) flash attention
    attn_kernel<<<dim3(NSEQ / 32, BHT), 256, ATTN_SMEM_BYTES>>>();

    // 4) output projection
    mm_kernel<0><<<dim3(DIM / 128, 8192 / 128), 256>>>(
        nullptr, proj_w, proj_b, out, BROWS, DIM, DIM);
}

// round 7
// speedup vs baseline: 4.0086x; 1.2323x over previous
#include <cuda_runtime.h>
#include <cstdint>

#define NHEADS 12
#define HD 64
#define BHT 96        // B * NHEADS
#define NSEQ 1024     // H*W
#define DIM 768
#define BROWS 8192    // B * NSEQ

// ---------------- scratch (device globals; no allocation) ----------------
__device__ float g_q[BHT * NSEQ * HD];   // tf32-rna-rounded values
__device__ float g_k[BHT * NSEQ * HD];   // tf32-rna-rounded values
__device__ float g_v[BHT * NSEQ * HD];   // tf32-rna-rounded values
__device__ float g_relh[BHT * 32 * 32 * 32];
__device__ float g_relw[BHT * 32 * 32 * 32];
__device__ float g_o[BROWS * DIM];

// ---------------- tf32 helpers --------------------------------------------
__device__ __forceinline__ unsigned f2tf32(float x) {
    unsigned y;
    asm("cvt.rna.tf32.f32 %0, %1;" : "=r"(y) : "f"(x));
    return y;
}
__device__ __forceinline__ unsigned u2tf32(unsigned x) {
    unsigned y;
    asm("cvt.rna.tf32.f32 %0, %1;" : "=r"(y) : "f"(__uint_as_float(x)));
    return y;
}

// D += A(16x8) @ B(8x8), tf32 in, f32 acc. m16n8k8 fragment layout.
__device__ __forceinline__ void mma_tf32(float* d,
                                         unsigned a0, unsigned a1, unsigned a2, unsigned a3,
                                         unsigned b0, unsigned b1)
{
    asm volatile(
        "mma.sync.aligned.m16n8k8.row.col.f32.tf32.tf32.f32 "
        "{%0,%1,%2,%3}, {%4,%5,%6,%7}, {%8,%9}, {%0,%1,%2,%3};"
        : "+f"(d[0]), "+f"(d[1]), "+f"(d[2]), "+f"(d[3])
        : "r"(a0), "r"(a1), "r"(a2), "r"(a3), "r"(b0), "r"(b1));
}

__device__ __forceinline__ void cp16(uint32_t dst, const void* src) {
    asm volatile("cp.async.cg.shared.global [%0], [%1], 16;" :: "r"(dst), "l"(src));
}

// ---------------- tf32 GEMM, 3-stage cp.async pipeline ---------------------
// BM=128, BN=128, BK=16, 256 threads, warp grid 2(m) x 4(n), warp tile 64x32.
// Fragments are rna-rounded to tf32 after the smem load.
#define MM_AS 2560            // 128*20 floats per stage
#define MM_BS 2176            // 16*136 floats per stage
#define MM_SMEM_FLOATS (3 * (MM_AS + MM_BS))
#define MM_SMEM_BYTES  (MM_SMEM_FLOATS * 4)

template <int MODE>
__global__ void __launch_bounds__(256, 2) mm_kernel(
    const float* __restrict__ Ain, const float* __restrict__ Bmat,
    const float* __restrict__ bias, float* __restrict__ C,
    int M, int N, int K)
{
    extern __shared__ float mmsm[];
    const float* A = (MODE == 0) ? (const float*)g_o : Ain;

    const int bm = blockIdx.y * 128;
    const int bn = blockIdx.x * 128;
    const int t  = threadIdx.x;
    const int w  = t >> 5;
    const int lane = t & 31;
    const int g  = lane >> 2;
    const int tg = lane & 3;
    const int wm = w >> 2;
    const int wn = w & 3;

    const int a_row = t >> 1;
    const int a_k   = (t & 1) * 8;
    const int b_k   = t >> 4;
    const int b_n   = (t & 15) * 8;

    const uint32_t sbase = (uint32_t)__cvta_generic_to_shared(mmsm);

    float acc[4][4][4];
#pragma unroll
    for (int i = 0; i < 4; i++)
#pragma unroll
        for (int j = 0; j < 4; j++)
#pragma unroll
            for (int q = 0; q < 4; q++) acc[i][j][q] = 0.f;

    const int nk = K / 16;

    auto issue = [&](int kt) {
        int buf = kt % 3;
        const float* ap = &A[(bm + a_row) * K + kt * 16 + a_k];
        uint32_t ad = sbase + (buf * MM_AS + a_row * 20 + a_k) * 4;
        cp16(ad, ap); cp16(ad + 16, ap + 4);
        const float* bp = &Bmat[(kt * 16 + b_k) * N + bn + b_n];
        uint32_t bd = sbase + (3 * MM_AS + buf * MM_BS + b_k * 136 + b_n) * 4;
        cp16(bd, bp); cp16(bd + 16, bp + 4);
        asm volatile("cp.async.commit_group;");
    };

    issue(0);
    issue(1);

    for (int kt = 0; kt < nk; kt++) {
        if (kt == nk - 1) asm volatile("cp.async.wait_group 0;");
        else              asm volatile("cp.async.wait_group 1;");
        __syncthreads();
        if (kt + 2 < nk) issue(kt + 2);

        const unsigned* as = (const unsigned*)(mmsm + (kt % 3) * MM_AS);
        const unsigned* bs = (const unsigned*)(mmsm + 3 * MM_AS + (kt % 3) * MM_BS);

#pragma unroll
        for (int ks = 0; ks < 2; ks++) {
            unsigned af[4][4];
#pragma unroll
            for (int mt = 0; mt < 4; mt++) {
                int r = wm * 64 + mt * 16 + g;
                af[mt][0] = u2tf32(as[r * 20 + ks * 8 + tg]);
                af[mt][1] = u2tf32(as[(r + 8) * 20 + ks * 8 + tg]);
                af[mt][2] = u2tf32(as[r * 20 + ks * 8 + tg + 4]);
                af[mt][3] = u2tf32(as[(r + 8) * 20 + ks * 8 + tg + 4]);
            }
            unsigned bf[4][2];
#pragma unroll
            for (int nt = 0; nt < 4; nt++) {
                int c = wn * 32 + nt * 8 + g;
                bf[nt][0] = u2tf32(bs[(ks * 8 + tg) * 136 + c]);
                bf[nt][1] = u2tf32(bs[(ks * 8 + tg + 4) * 136 + c]);
            }
#pragma unroll
            for (int mt = 0; mt < 4; mt++)
#pragma unroll
                for (int nt = 0; nt < 4; nt++)
                    mma_tf32(acc[mt][nt], af[mt][0], af[mt][1], af[mt][2], af[mt][3],
                             bf[nt][0], bf[nt][1]);
        }
    }

#pragma unroll
    for (int mt = 0; mt < 4; mt++) {
#pragma unroll
        for (int nt = 0; nt < 4; nt++) {
            int row = bm + wm * 64 + mt * 16 + g;
            int col = bn + wn * 32 + nt * 8 + 2 * tg;
#pragma unroll
            for (int q = 0; q < 4; q++) {
                int r = row + (q >> 1) * 8;
                int c = col + (q & 1);
                float v = acc[mt][nt][q] + bias[c];
                if (MODE == 0) {
                    C[r * N + c] = v;
                } else {
                    const int b = r >> 10;
                    const int n = r & 1023;
                    const int which = c / 768;
                    const int rem = c - which * 768;
                    const int head = rem >> 6;
                    const int d = rem & 63;
                    float* dst = (which == 0) ? g_q : (which == 1) ? g_k : g_v;
                    // rna-rounded so attention can use raw bits directly
                    dst[((b * NHEADS + head) * NSEQ + n) * HD + d] =
                        __uint_as_float(f2tf32(v));
                }
            }
        }
    }
}

// ---------------- relative position bias: one block per (bh, qh) ----------
__global__ void __launch_bounds__(256) rel_kernel(
    const float* __restrict__ rph, const float* __restrict__ rpw)
{
    __shared__ float qrow[32 * 64];
    __shared__ float rh[32 * 65];
    __shared__ float rw[63 * 65];

    const int bh = blockIdx.x;
    const int qh = blockIdx.y;
    const int t  = threadIdx.x;

    for (int i = t; i < 32 * 64; i += 256) {
        int row = i >> 6, d = i & 63;
        qrow[i] = g_q[((bh * NSEQ) + qh * 32 + row) * HD + d];
        rh[row * 65 + d] = rph[(qh + row) * 64 + d];
    }
    for (int i = t; i < 63 * 64; i += 256) {
        int row = i >> 6, d = i & 63;
        rw[row * 65 + d] = rpw[i];
    }
    __syncthreads();

    for (int o = t; o < 2048; o += 256) {
        if (o < 1024) {
            int qw = o >> 5, kh = o & 31;
            const float* a  = &qrow[qw * 64];
            const float* b2 = &rh[(31 - kh) * 65];
            float s = 0.f;
#pragma unroll
            for (int d = 0; d < 64; d++) s += a[d] * b2[d];
            g_relh[(((bh * 32 + qh) * 32 + qw) * 32) + kh] = s;
        } else {
            int oo = o - 1024;
            int qw = oo >> 5, kw = oo & 31;
            const float* a  = &qrow[qw * 64];
            const float* b2 = &rw[(qw - kw + 31) * 65];
            float s = 0.f;
#pragma unroll
            for (int d = 0; d < 64; d++) s += a[d] * b2[d];
            g_relw[(((bh * 32 + qh) * 32 + qw) * 32) + kw] = s;
        }
    }
}

// ---------------- attention: QT=64 queries, KT=64 key tiles, no-max softmax
// Q/K/V values are pre-rounded to tf32 -> raw-bit copy is exact.
// smem float offsets
#define SM_QS     0                        // [64][68]  = 4352
#define SM_RELH   4352                     // [64][32]  = 2048
#define SM_RELW   6400                     // [64][32]  = 2048
#define SM_SSUM   8448                     // [4][64]   = 256
#define SM_P      8704                     // [64][68]  = 4352
#define SM_K      13056                    // [64][68]  = 4352
#define SM_V      17408                    // [64][72]  = 4608
#define ATTN_SMEM_FLOATS 22016             // 88,064 B
#define ATTN_SMEM_BYTES  (ATTN_SMEM_FLOATS * 4)

__global__ void __launch_bounds__(256, 2) attn_kernel()
{
    extern __shared__ float sm[];
    unsigned* Qu  = (unsigned*)(sm + SM_QS);
    float* RH     = sm + SM_RELH;
    float* RW     = sm + SM_RELW;
    float* SS     = sm + SM_SSUM;
    unsigned* Pu  = (unsigned*)(sm + SM_P);
    unsigned* Ku  = (unsigned*)(sm + SM_K);
    unsigned* Vu  = (unsigned*)(sm + SM_V);

    const int qt = blockIdx.x;   // 0..15 (64 q rows each)
    const int bh = blockIdx.y;   // 0..95
    const int t  = threadIdx.x;
    const int w  = t >> 5;
    const int lane = t & 31;
    const int g  = lane >> 2;
    const int tg = lane & 3;
    // S-phase warp grid: 2(m) x 4(n)
    const int wm = w >> 2;
    const int wn = w & 3;
    // PV-phase warp grid: 4(row-groups) x 2(d-halves)
    const int wr = w >> 1;
    const int wd = w & 1;
    const float scale = 0.125f;

    // load Q tile (64x64, tf32-rounded bits)
#pragma unroll
    for (int f = 0; f < 4; f++) {
        int i = t + 256 * f;
        int r = i >> 4;
        int c = (i & 15) * 4;
        *(uint4*)&Qu[r * 68 + c] =
            *(const uint4*)&g_q[(bh * NSEQ + qt * 64 + r) * HD + c];
    }
    // rel bias rows for 64 q rows
    for (int i = t; i < 64 * 32; i += 256) {
        int r = i >> 5, c = i & 31;
        int qn = qt * 64 + r;
        int qh = qn >> 5, qw = qn & 31;
        int base = ((bh * 32 + qh) * 32 + qw) * 32 + c;
        RH[i] = g_relh[base];
        RW[i] = g_relw[base];
    }

    // prologue K/V prefetch (tile 0)
    uint4 kst[4], vst[4];
#pragma unroll
    for (int f = 0; f < 4; f++) {
        int fi = t + 256 * f;
        int row = fi >> 4;
        int col = (fi & 15) * 4;
        kst[f] = *(const uint4*)&g_k[(bh * NSEQ + row) * HD + col];
        vst[f] = *(const uint4*)&g_v[(bh * NSEQ + row) * HD + col];
    }

    float rsum[2][2] = {{0.f, 0.f}, {0.f, 0.f}};
    float po[4][4];
#pragma unroll
    for (int i = 0; i < 4; i++)
#pragma unroll
        for (int q = 0; q < 4; q++) po[i][q] = 0.f;

    for (int kt = 0; kt < 16; kt++) {
        // store K/V tile
#pragma unroll
        for (int f = 0; f < 4; f++) {
            int fi = t + 256 * f;
            int row = fi >> 4;
            int col = (fi & 15) * 4;
            *(uint4*)&Ku[row * 68 + col] = kst[f];
            *(uint4*)&Vu[row * 72 + col] = vst[f];
        }
        __syncthreads();   // tile ready (also covers Q/rel on kt==0)

        // prefetch next tile
        if (kt + 1 < 16) {
#pragma unroll
            for (int f = 0; f < 4; f++) {
                int fi = t + 256 * f;
                int row = fi >> 4;
                int col = (fi & 15) * 4;
                kst[f] = *(const uint4*)&g_k[(bh * NSEQ + (kt + 1) * 64 + row) * HD + col];
                vst[f] = *(const uint4*)&g_v[(bh * NSEQ + (kt + 1) * 64 + row) * HD + col];
            }
        }

        // ---- S = Q @ K^T : warp (wm,wn) owns rows wm*32+.., keys wn*16+.. --
        float acc[2][2][4];
#pragma unroll
        for (int i = 0; i < 2; i++)
#pragma unroll
            for (int j = 0; j < 2; j++)
#pragma unroll
                for (int q = 0; q < 4; q++) acc[i][j][q] = 0.f;

#pragma unroll
        for (int ks = 0; ks < 8; ks++) {
            unsigned af[2][4];
#pragma unroll
            for (int mt = 0; mt < 2; mt++) {
                int r = wm * 32 + mt * 16 + g;
                int c = ks * 8 + tg;
                af[mt][0] = Qu[r * 68 + c];
                af[mt][1] = Qu[(r + 8) * 68 + c];
                af[mt][2] = Qu[r * 68 + c + 4];
                af[mt][3] = Qu[(r + 8) * 68 + c + 4];
            }
            unsigned bf[2][2];
#pragma unroll
            for (int nt = 0; nt < 2; nt++) {
                int key = wn * 16 + nt * 8 + g;
                bf[nt][0] = Ku[key * 68 + ks * 8 + tg];
                bf[nt][1] = Ku[key * 68 + ks * 8 + tg + 4];
            }
#pragma unroll
            for (int mt = 0; mt < 2; mt++)
#pragma unroll
                for (int nt = 0; nt < 2; nt++)
                    mma_tf32(acc[mt][nt], af[mt][0], af[mt][1], af[mt][2], af[mt][3],
                             bf[nt][0], bf[nt][1]);
        }

        // ---- P = exp(scale*S + bias); accumulate private row sums ---------
#pragma unroll
        for (int mt = 0; mt < 2; mt++)
#pragma unroll
            for (int nt = 0; nt < 2; nt++)
#pragma unroll
                for (int q = 0; q < 4; q++) {
                    int rh = q >> 1;
                    int rr = wm * 32 + mt * 16 + g + rh * 8;
                    int cl = wn * 16 + nt * 8 + 2 * tg + (q & 1);
                    int cc = kt * 64 + cl;
                    int kh = cc >> 5, kw = cc & 31;
                    float e = __expf(acc[mt][nt][q] * scale
                                     + RH[rr * 32 + kh] + RW[rr * 32 + kw]);
                    rsum[mt][rh] += e;
                    Pu[rr * 68 + cl] = f2tf32(e);   // rna-round P for PV MMA
                }
        __syncthreads();   // P ready

        // ---- PV: warp (wr,wd) owns rows wr*16+.., out dims wd*32+.. --------
#pragma unroll
        for (int ks = 0; ks < 8; ks++) {
            int pb = (wr * 16 + g) * 68 + ks * 8 + tg;
            unsigned a0 = Pu[pb];
            unsigned a1 = Pu[pb + 8 * 68];
            unsigned a2 = Pu[pb + 4];
            unsigned a3 = Pu[pb + 8 * 68 + 4];
#pragma unroll
            for (int nt = 0; nt < 4; nt++) {
                unsigned b0 = Vu[(ks * 8 + tg) * 72 + wd * 32 + nt * 8 + g];
                unsigned b1 = Vu[(ks * 8 + tg + 4) * 72 + wd * 32 + nt * 8 + g];
                mma_tf32(po[nt], a0, a1, a2, a3, b0, b1);
            }
        }
        __syncthreads();   // K/V/P buffers free
    }

    // ---- row-sum reduction across wn warps ---------------------------------
#pragma unroll
    for (int mt = 0; mt < 2; mt++)
#pragma unroll
        for (int rh = 0; rh < 2; rh++) {
            float v = rsum[mt][rh];
            v += __shfl_xor_sync(0xffffffffu, v, 1);
            v += __shfl_xor_sync(0xffffffffu, v, 2);
            if (tg == 0) SS[wn * 64 + wm * 32 + mt * 16 + g + rh * 8] = v;
        }
    __syncthreads();

    // ---- epilogue: normalize, write g_o [b][n][head][d] ---------------------
    const int b = bh / NHEADS;
    const int head = bh % NHEADS;
    const int r0 = wr * 16 + g;
    const int r1 = r0 + 8;
    float s0 = SS[r0] + SS[64 + r0] + SS[128 + r0] + SS[192 + r0];
    float s1 = SS[r1] + SS[64 + r1] + SS[128 + r1] + SS[192 + r1];
    float i0 = 1.0f / s0;
    float i1 = 1.0f / s1;
#pragma unroll
    for (int nt = 0; nt < 4; nt++) {
        int dim = head * HD + wd * 32 + nt * 8 + 2 * tg;
        long o0 = (long)(b * NSEQ + qt * 64 + r0) * DIM + dim;
        long o1 = (long)(b * NSEQ + qt * 64 + r1) * DIM + dim;
        g_o[o0]     = po[nt][0] * i0;
        g_o[o0 + 1] = po[nt][1] * i0;
        g_o[o1]     = po[nt][2] * i1;
        g_o[o1 + 1] = po[nt][3] * i1;
    }
}

// ---------------- launch ---------------------------------------------------
extern "C" void kernel_launch(void* const* d_in, const int* in_sizes, int n_in,
                              void* d_out, int out_size)
{
    const float* x      = (const float*)d_in[0];
    const float* qkv_w  = (const float*)d_in[1];
    const float* qkv_b  = (const float*)d_in[2];
    const float* proj_w = (const float*)d_in[3];
    const float* proj_b = (const float*)d_in[4];
    const float* rph    = (const float*)d_in[5];
    const float* rpw    = (const float*)d_in[6];
    float* out = (float*)d_out;

    cudaFuncSetAttribute(attn_kernel,
                         cudaFuncAttributeMaxDynamicSharedMemorySize,
                         ATTN_SMEM_BYTES);
    cudaFuncSetAttribute(mm_kernel<1>,
                         cudaFuncAttributeMaxDynamicSharedMemorySize,
                         MM_SMEM_BYTES);
    cudaFuncSetAttribute(mm_kernel<0>,
                         cudaFuncAttributeMaxDynamicSharedMemorySize,
                         MM_SMEM_BYTES);

    // 1) QKV projection: (8192,768) @ (768,2304) -> scatter to q/k/v (rounded)
    mm_kernel<1><<<dim3(2304 / 128, 8192 / 128), 256, MM_SMEM_BYTES>>>(
        x, qkv_w, qkv_b, nullptr, BROWS, 3 * DIM, DIM);

    // 2) decomposed relative position bias
    rel_kernel<<<dim3(BHT, 32), 256>>>(rph, rpw);

    // 3) attention (no-max online softmax), 64-query x 64-key tiles
    attn_kernel<<<dim3(NSEQ / 64, BHT), 256, ATTN_SMEM_BYTES>>>();

    // 4) output projection: (8192,768) @ (768,768) + bias -> d_out
    mm_kernel<0><<<dim3(DIM / 128, 8192 / 128), 256, MM_SMEM_BYTES>>>(
        nullptr, proj_w, proj_b, out, BROWS, DIM, DIM);
}